// round 9
// baseline (speedup 1.0000x reference)
#include <cuda_runtime.h>
#include <cuda_fp16.h>
#include <cstdint>

// ============================================================================
// IWConLoss on GB300 (sm_103a via compute_103 baseline PTX):
//   scores = Q @ Neg^T / tau ; loss = mean( LSE_row(scores) - (Q.P)/tau )
// R8: C double-buffer + epilogue interleaved INTO the ks/MMA loop (fills HMMA
// slack with MUFU/FMA), 3-stage cp.async ring with single sync per tile.
// ============================================================================

static constexpr int NQ   = 8192;
static constexpr int NNEG = 16384;
static constexpr int KD   = 128;

static constexpr int MB = 128;      // query rows per CTA
static constexpr int NT = 64;       // negatives per tile
static constexpr int SPLITS = 16;   // grid = 64 x 16 = 1024 CTAs
static constexpr int RB = NQ / MB;  // 64 row blocks
static constexpr int TILES = NNEG / SPLITS / NT;   // 16
static constexpr int STAGES = 3;

static constexpr int PITCH = 272;                   // 128 fp16 + 8 pad
static constexpr int QT_BYTES = 128 * PITCH;        // 34816
static constexpr int NT_BYTES = NT * PITCH;         // 17408
static constexpr int SMEM_TOTAL = QT_BYTES + STAGES * NT_BYTES;  // 87040 -> 2 CTAs/SM

static constexpr float INV_TAU = 5.0f;
static constexpr float C_T  = 7.2134752044448170f;  // log2(e)/tau
static constexpr float LN2F = 0.69314718055994531f;

// ---------------- device scratch ----------------
__device__ __align__(16) __half g_qh[NQ * KD];
__device__ __align__(16) __half g_nh[NNEG * KD];
__device__ float g_poslogit[NQ];
__device__ float g_pm[SPLITS * NQ];     // [split][row]
__device__ float g_ps[SPLITS * NQ];
__device__ double g_part[RB];
__device__ int g_rbctr[RB];
__device__ int g_ctr;

// ---------------- helpers ----------------
__device__ __forceinline__ uint32_t smem_u32(const void* p) {
    uint32_t a;
    asm("{ .reg .u64 t; cvta.to.shared.u64 t, %1; cvt.u32.u64 %0, t; }"
        : "=r"(a) : "l"(p));
    return a;
}
__device__ __forceinline__ float ex2f(float x) {
    float r; asm("ex2.approx.ftz.f32 %0, %1;" : "=f"(r) : "f"(x)); return r;
}
__device__ __forceinline__ void cpa16(uint32_t dst, const void* src) {
    asm volatile("cp.async.cg.shared.global [%0], [%1], 16;" :: "r"(dst), "l"(src));
}
#define CP_COMMIT() asm volatile("cp.async.commit_group;" ::: "memory")
#define CP_WAIT(n)  asm volatile("cp.async.wait_group %0;" :: "n"(n) : "memory")

__device__ __forceinline__ void ldsm4(uint32_t& r0, uint32_t& r1, uint32_t& r2,
                                      uint32_t& r3, uint32_t addr) {
    asm volatile("ldmatrix.sync.aligned.m8n8.x4.shared.b16 {%0,%1,%2,%3}, [%4];"
        : "=r"(r0), "=r"(r1), "=r"(r2), "=r"(r3) : "r"(addr));
}
__device__ __forceinline__ void mma16816(float* d, const uint32_t* a,
                                         const uint32_t b0, const uint32_t b1) {
    asm volatile(
        "mma.sync.aligned.m16n8k16.row.col.f32.f16.f16.f32 "
        "{%0,%1,%2,%3}, {%4,%5,%6,%7}, {%8,%9}, {%0,%1,%2,%3};"
        : "+f"(d[0]), "+f"(d[1]), "+f"(d[2]), "+f"(d[3])
        : "r"(a[0]), "r"(a[1]), "r"(a[2]), "r"(a[3]), "r"(b0), "r"(b1));
}

// ============================================================================
// combined prep kernel
// ============================================================================
static constexpr int NB_NEG = (NNEG * KD) / 1024;   // 2048 blocks

__global__ void prep_kernel(const float* __restrict__ q, const float* __restrict__ pos,
                            const float* __restrict__ neg) {
    if (blockIdx.x < NB_NEG) {
        int i = (blockIdx.x * 256 + threadIdx.x) * 4;
        float4 v = *reinterpret_cast<const float4*>(neg + i);
        __half2* o = reinterpret_cast<__half2*>(g_nh + i);
        o[0] = __floats2half2_rn(v.x, v.y);
        o[1] = __floats2half2_rn(v.z, v.w);
    } else {
        int b = blockIdx.x - NB_NEG;
        int w = threadIdx.x >> 5, lane = threadIdx.x & 31;
        int row = b * 8 + w;
        const float4 q4 = *reinterpret_cast<const float4*>(q + row * KD + lane * 4);
        const float4 p4 = *reinterpret_cast<const float4*>(pos + row * KD + lane * 4);
        float d = q4.x * p4.x + q4.y * p4.y + q4.z * p4.z + q4.w * p4.w;
        #pragma unroll
        for (int o = 16; o > 0; o >>= 1) d += __shfl_xor_sync(0xffffffffu, d, o);
        if (lane == 0) g_poslogit[row] = d * INV_TAU;

        __half2* o = reinterpret_cast<__half2*>(g_qh + row * KD + lane * 4);
        o[0] = __floats2half2_rn(q4.x * C_T, q4.y * C_T);
        o[1] = __floats2half2_rn(q4.z * C_T, q4.w * C_T);
    }
}

// ============================================================================
// main fused kernel
// ============================================================================
__device__ __forceinline__ void copy_q_block(uint32_t sb, int tid, int qbase) {
    #pragma unroll
    for (int j = 0; j < 8; j++) {
        int idx = j * 256 + tid;
        int row = idx >> 4, c = idx & 15;
        cpa16(sb + (uint32_t)(row * PITCH + c * 16), g_qh + (qbase + row) * KD + c * 8);
    }
}
__device__ __forceinline__ void copy_neg_tile(uint32_t sb, int tid, int stage, int rowbase) {
    uint32_t base = sb + (uint32_t)(QT_BYTES + NT_BYTES * stage);
    #pragma unroll
    for (int j = 0; j < 4; j++) {
        int idx = j * 256 + tid;
        int row = idx >> 4, c = idx & 15;
        cpa16(base + (uint32_t)(row * PITCH + c * 16),
              g_nh + (rowbase + row) * KD + c * 8);
    }
}

// one LSE row-slot (8 scores) — called inside the ks loop to interleave
template <int J>
__device__ __forceinline__ void epi_slot(const float C[2][4][4],
                                         float* mrun, float* srun, bool valid) {
    if (!valid) return;
    const int mi = J >> 1, hi = (J & 1) * 2;
    float x0 = C[mi][0][hi],     x1 = C[mi][0][hi + 1];
    float x2 = C[mi][1][hi],     x3 = C[mi][1][hi + 1];
    float x4 = C[mi][2][hi],     x5 = C[mi][2][hi + 1];
    float x6 = C[mi][3][hi],     x7 = C[mi][3][hi + 1];
    float tmax = fmaxf(fmaxf(fmaxf(x0, x1), fmaxf(x2, x3)),
                       fmaxf(fmaxf(x4, x5), fmaxf(x6, x7)));
    if (tmax > mrun[J]) {
        srun[J] *= ex2f(mrun[J] - tmax);
        mrun[J] = tmax;
    }
    const float mn = mrun[J];
    srun[J] += ex2f(x0 - mn) + ex2f(x1 - mn) + ex2f(x2 - mn) + ex2f(x3 - mn)
             + ex2f(x4 - mn) + ex2f(x5 - mn) + ex2f(x6 - mn) + ex2f(x7 - mn);
}

// full epilogue (used once for the final tile)
__device__ __forceinline__ void epilogue(const float C[2][4][4], float* mrun, float* srun) {
    epi_slot<0>(C, mrun, srun, true);
    epi_slot<1>(C, mrun, srun, true);
    epi_slot<2>(C, mrun, srun, true);
    epi_slot<3>(C, mrun, srun, true);
}

// one tile: MMA into Cc while interleaving the previous tile's epilogue (Cp)
__device__ __forceinline__ void tile_body(
    int t, uint32_t sb, int tid, uint32_t aBase, uint32_t bOff, int negbase,
    float (&Cc)[2][4][4], float (&Cp)[2][4][4],
    float* mrun, float* srun, bool doEpi)
{
    CP_WAIT(1);                       // tile t resident (<=1 group pending)
    __syncthreads();                  // single barrier per tile

    // prefetch t+2 into the stage consumed at t-1 (drained by the sync above)
    if (t + 2 < TILES)
        copy_neg_tile(sb, tid, (t + 2) % STAGES, negbase + (t + 2) * NT);
    CP_COMMIT();

    #pragma unroll
    for (int mi = 0; mi < 2; mi++)
        #pragma unroll
        for (int ni = 0; ni < 4; ni++)
            #pragma unroll
            for (int r = 0; r < 4; r++) Cc[mi][ni][r] = 0.0f;

    const uint32_t bBase = sb + (uint32_t)(QT_BYTES + NT_BYTES * (t % STAGES)) + bOff;

    #pragma unroll
    for (int ks = 0; ks < 8; ks++) {
        uint32_t A[2][4], B[2][4];
        #pragma unroll
        for (int mi = 0; mi < 2; mi++)
            ldsm4(A[mi][0], A[mi][1], A[mi][2], A[mi][3],
                  aBase + (uint32_t)(mi * 16 * PITCH + ks * 32));
        #pragma unroll
        for (int np = 0; np < 2; np++)
            ldsm4(B[np][0], B[np][1], B[np][2], B[np][3],
                  bBase + (uint32_t)(np * 16 * PITCH + ks * 32));
        #pragma unroll
        for (int mi = 0; mi < 2; mi++)
            #pragma unroll
            for (int ni = 0; ni < 4; ni++)
                mma16816(Cc[mi][ni], A[mi],
                         B[ni >> 1][(ni & 1) * 2], B[ni >> 1][(ni & 1) * 2 + 1]);

        // interleave one epilogue row-slot of the previous tile after odd ks
        if (ks == 1) epi_slot<0>(Cp, mrun, srun, doEpi);
        if (ks == 3) epi_slot<1>(Cp, mrun, srun, doEpi);
        if (ks == 5) epi_slot<2>(Cp, mrun, srun, doEpi);
        if (ks == 7) epi_slot<3>(Cp, mrun, srun, doEpi);
    }
}

__global__ __launch_bounds__(256, 2) void conloss_main_kernel(float* __restrict__ out) {
    extern __shared__ char smem[];
    uint32_t sb = smem_u32(smem);
    const int tid = threadIdx.x, warp = tid >> 5, lane = tid & 31;
    const int wm = warp & 3;          // 4 warp-rows of 32
    const int wn = warp >> 2;         // 2 warp-cols of 32
    const int rb = blockIdx.x;
    const int qbase = rb * MB;
    const int negbase = blockIdx.y * (NNEG / SPLITS);

    copy_q_block(sb, tid, qbase);
    copy_neg_tile(sb, tid, 0, negbase);
    CP_COMMIT();                                  // group: Q + tile0
    copy_neg_tile(sb, tid, 1, negbase + NT);
    CP_COMMIT();                                  // group: tile1

    const uint32_t aBase = sb + (uint32_t)((wm * 32 + (lane & 15)) * PITCH + ((lane >> 4) * 16));
    const uint32_t bOff = (uint32_t)(((wn * 32) + (lane & 7) + ((lane >> 4) << 3)) * PITCH
                                     + (((lane >> 3) & 1) * 16));

    float C0[2][4][4], C1[2][4][4];
    float mrun[4], srun[4];
    #pragma unroll
    for (int j = 0; j < 4; j++) { mrun[j] = -1e30f; srun[j] = 0.0f; }

    #pragma unroll 1
    for (int t = 0; t < TILES; t += 2) {
        tile_body(t,     sb, tid, aBase, bOff, negbase, C0, C1, mrun, srun, t > 0);
        tile_body(t + 1, sb, tid, aBase, bOff, negbase, C1, C0, mrun, srun, true);
    }
    epilogue(C1, mrun, srun);     // last tile (TILES even -> lives in C1)

    // combine the 4 lanes sharing each row
    #pragma unroll
    for (int j = 0; j < 4; j++) {
        #pragma unroll
        for (int off = 1; off <= 2; off <<= 1) {
            float mo = __shfl_xor_sync(0xffffffffu, mrun[j], off);
            float so = __shfl_xor_sync(0xffffffffu, srun[j], off);
            float M = fmaxf(mrun[j], mo);
            srun[j] = srun[j] * ex2f(mrun[j] - M) + so * ex2f(mo - M);
            mrun[j] = M;
        }
    }

    __syncthreads();
    float* smm = reinterpret_cast<float*>(smem);          // [2][128]
    float* sms = smm + 256;
    if ((lane & 3) == 0) {
        #pragma unroll
        for (int j = 0; j < 4; j++) {
            int row = wm * 32 + (j >> 1) * 16 + (j & 1) * 8 + (lane >> 2);
            smm[wn * 128 + row] = mrun[j];
            sms[wn * 128 + row] = srun[j];
        }
    }
    __syncthreads();
    if (tid < 128) {
        float m0 = smm[tid], m1 = smm[128 + tid];
        float M = fmaxf(m0, m1);
        float S = sms[tid] * ex2f(m0 - M) + sms[128 + tid] * ex2f(m1 - M);
        int grow = qbase + tid;
        g_pm[blockIdx.y * NQ + grow] = M;
        g_ps[blockIdx.y * NQ + grow] = S;
    }

    // ---------------- fused reduction ----------------
    __threadfence();
    __shared__ int lastRb;
    if (tid == 0)
        lastRb = (atomicAdd(&g_rbctr[rb], 1) == SPLITS - 1);
    __syncthreads();
    if (!lastRb) return;

    __threadfence();
    double part = 0.0;
    if (tid < 128) {
        int r = qbase + tid;
        float m[SPLITS], s[SPLITS];
        #pragma unroll
        for (int j = 0; j < SPLITS; j++) {
            m[j] = g_pm[j * NQ + r];
            s[j] = g_ps[j * NQ + r];
        }
        float M = m[0];
        #pragma unroll
        for (int j = 1; j < SPLITS; j++) M = fmaxf(M, m[j]);
        float S = 0.0f;
        #pragma unroll
        for (int j = 0; j < SPLITS; j++) S += s[j] * ex2f(m[j] - M);
        float lse = LN2F * (M + log2f(S));
        part = (double)(lse - g_poslogit[r]);
    }
    double* shd = reinterpret_cast<double*>(smem);
    shd[tid] = part;
    __syncthreads();
    for (int o = 128; o > 0; o >>= 1) {
        if (tid < o) shd[tid] += shd[tid + o];
        __syncthreads();
    }
    if (tid == 0) {
        g_part[rb] = shd[0];
        g_rbctr[rb] = 0;
        __threadfence();
        if (atomicAdd(&g_ctr, 1) == RB - 1) {
            __threadfence();
            double acc = 0.0;
            #pragma unroll
            for (int i = 0; i < RB; i++) acc += g_part[i];
            out[0] = (float)(acc / (double)NQ);
            g_ctr = 0;
        }
    }
}

// ============================================================================
// kernel_launch
// ============================================================================
extern "C" void kernel_launch(void* const* d_in, const int* in_sizes, int n_in,
                              void* d_out, int out_size) {
    (void)n_in; (void)out_size;
    const float* a0 = (const float*)d_in[0];
    const float* a1 = (const float*)d_in[1];
    const float* a2 = (const float*)d_in[2];
    const float *q, *p, *neg;
    if (in_sizes[2] == NNEG * KD)      { q = a0; p = a1; neg = a2; }
    else if (in_sizes[1] == NNEG * KD) { q = a0; p = a2; neg = a1; }
    else                               { q = a1; p = a2; neg = a0; }

    cudaFuncSetAttribute(conloss_main_kernel,
                         cudaFuncAttributeMaxDynamicSharedMemorySize, SMEM_TOTAL);

    prep_kernel<<<NB_NEG + NQ / 8, 256>>>(q, p, neg);
    conloss_main_kernel<<<dim3(RB, SPLITS), 256, SMEM_TOTAL>>>((float*)d_out);
}

// round 10
// speedup vs baseline: 1.0832x; 1.0832x over previous
#include <cuda_runtime.h>
#include <cuda_fp16.h>
#include <cstdint>

// ============================================================================
// IWConLoss on GB300 (sm_103a via compute_103 baseline PTX):
//   scores = Q @ Neg^T / tau ; loss = mean( LSE_row(scores) - (Q.P)/tau )
// R9: R6 geometry (occ3, NT=64, 2 stages) but barrier-free mainloop:
// mbarrier producer/consumer pipeline (full: cp.async noinc x256, empty: 8 warp
// arrives). Warps decouple; no full-CTA reconvergence per tile.
// ============================================================================

static constexpr int NQ   = 8192;
static constexpr int NNEG = 16384;
static constexpr int KD   = 128;

static constexpr int MB = 128;      // query rows per CTA
static constexpr int NT = 64;       // negatives per tile
static constexpr int SPLITS = 16;   // grid = 64 x 16 = 1024 CTAs
static constexpr int RB = NQ / MB;  // 64 row blocks
static constexpr int TILES = NNEG / SPLITS / NT;   // 16
static constexpr int STAGES = 2;

static constexpr int PITCH = 272;                   // 128 fp16 + 8 pad
static constexpr int QT_BYTES = 128 * PITCH;        // 34816
static constexpr int NT_BYTES = NT * PITCH;         // 17408
static constexpr int MBAR_BASE = QT_BYTES + STAGES * NT_BYTES;   // 69632
static constexpr int SMEM_TOTAL = MBAR_BASE + 64;   // 69696 -> 3 CTAs/SM

static constexpr float INV_TAU = 5.0f;
static constexpr float C_T  = 7.2134752044448170f;  // log2(e)/tau
static constexpr float LN2F = 0.69314718055994531f;

// ---------------- device scratch ----------------
__device__ __align__(16) __half g_qh[NQ * KD];
__device__ __align__(16) __half g_nh[NNEG * KD];
__device__ float g_poslogit[NQ];
__device__ float g_pm[SPLITS * NQ];     // [split][row]
__device__ float g_ps[SPLITS * NQ];
__device__ double g_part[RB];
__device__ int g_rbctr[RB];
__device__ int g_ctr;

// ---------------- helpers ----------------
__device__ __forceinline__ uint32_t smem_u32(const void* p) {
    uint32_t a;
    asm("{ .reg .u64 t; cvta.to.shared.u64 t, %1; cvt.u32.u64 %0, t; }"
        : "=r"(a) : "l"(p));
    return a;
}
__device__ __forceinline__ float ex2f(float x) {
    float r; asm("ex2.approx.ftz.f32 %0, %1;" : "=f"(r) : "f"(x)); return r;
}
__device__ __forceinline__ void cpa16(uint32_t dst, const void* src) {
    asm volatile("cp.async.cg.shared.global [%0], [%1], 16;" :: "r"(dst), "l"(src));
}
// arrive-on-completion of all my prior cp.asyncs; expected count pre-set (.noinc)
__device__ __forceinline__ void cpa_arrive(uint32_t mbar) {
    asm volatile("cp.async.mbarrier.arrive.noinc.shared.b64 [%0];"
                 :: "r"(mbar) : "memory");
}
#define MBARRIER_INIT(addr, cnt) \
    asm volatile("mbarrier.init.shared.b64 [%0], %1;" :: "r"((uint32_t)(addr)), "r"((uint32_t)(cnt)) : "memory")
#define MBARRIER_ARRIVE(addr) \
    asm volatile("mbarrier.arrive.shared.b64 _, [%0];" :: "r"((uint32_t)(addr)) : "memory")
#define MBARRIER_WAIT_PARITY(mbar_smem_addr, phase_parity) do { \
    uint32_t _mbar = (uint32_t)(mbar_smem_addr); \
    uint32_t _parity = (uint32_t)(phase_parity); \
    uint32_t _done; \
    asm volatile("{\n\t.reg .pred p;\n\t" \
        "mbarrier.try_wait.parity.acquire.cta.shared::cta.b64 p, [%1], %2;\n\t" \
        "selp.b32 %0, 1, 0, p;\n\t}" \
        : "=r"(_done) : "r"(_mbar), "r"(_parity) : "memory"); \
    if (!_done) { \
        asm volatile("{\n\t.reg .pred P1;\n\t" \
            "WAIT_LOOP_%=:\n\t" \
            "mbarrier.try_wait.parity.acquire.cta.shared::cta.b64 P1, [%0], %1, 0x989680;\n\t" \
            "@P1 bra.uni WAIT_DONE_%=;\n\t" \
            "bra.uni WAIT_LOOP_%=;\n\t" \
            "WAIT_DONE_%=:\n\t}" \
            :: "r"(_mbar), "r"(_parity) : "memory"); \
    } \
} while (0)

__device__ __forceinline__ void ldsm4(uint32_t& r0, uint32_t& r1, uint32_t& r2,
                                      uint32_t& r3, uint32_t addr) {
    asm volatile("ldmatrix.sync.aligned.m8n8.x4.shared.b16 {%0,%1,%2,%3}, [%4];"
        : "=r"(r0), "=r"(r1), "=r"(r2), "=r"(r3) : "r"(addr));
}
__device__ __forceinline__ void mma16816(float* d, const uint32_t* a,
                                         const uint32_t b0, const uint32_t b1) {
    asm volatile(
        "mma.sync.aligned.m16n8k16.row.col.f32.f16.f16.f32 "
        "{%0,%1,%2,%3}, {%4,%5,%6,%7}, {%8,%9}, {%0,%1,%2,%3};"
        : "+f"(d[0]), "+f"(d[1]), "+f"(d[2]), "+f"(d[3])
        : "r"(a[0]), "r"(a[1]), "r"(a[2]), "r"(a[3]), "r"(b0), "r"(b1));
}

// ============================================================================
// combined prep kernel
// ============================================================================
static constexpr int NB_NEG = (NNEG * KD) / 1024;   // 2048 blocks

__global__ void prep_kernel(const float* __restrict__ q, const float* __restrict__ pos,
                            const float* __restrict__ neg) {
    if (blockIdx.x < NB_NEG) {
        int i = (blockIdx.x * 256 + threadIdx.x) * 4;
        float4 v = *reinterpret_cast<const float4*>(neg + i);
        __half2* o = reinterpret_cast<__half2*>(g_nh + i);
        o[0] = __floats2half2_rn(v.x, v.y);
        o[1] = __floats2half2_rn(v.z, v.w);
    } else {
        int b = blockIdx.x - NB_NEG;
        int w = threadIdx.x >> 5, lane = threadIdx.x & 31;
        int row = b * 8 + w;
        const float4 q4 = *reinterpret_cast<const float4*>(q + row * KD + lane * 4);
        const float4 p4 = *reinterpret_cast<const float4*>(pos + row * KD + lane * 4);
        float d = q4.x * p4.x + q4.y * p4.y + q4.z * p4.z + q4.w * p4.w;
        #pragma unroll
        for (int o = 16; o > 0; o >>= 1) d += __shfl_xor_sync(0xffffffffu, d, o);
        if (lane == 0) g_poslogit[row] = d * INV_TAU;

        __half2* o = reinterpret_cast<__half2*>(g_qh + row * KD + lane * 4);
        o[0] = __floats2half2_rn(q4.x * C_T, q4.y * C_T);
        o[1] = __floats2half2_rn(q4.z * C_T, q4.w * C_T);
    }
}

// ============================================================================
// main fused kernel
// ============================================================================
__device__ __forceinline__ void copy_q_block(uint32_t sb, int tid, int qbase) {
    #pragma unroll
    for (int j = 0; j < 8; j++) {
        int idx = j * 256 + tid;
        int row = idx >> 4, c = idx & 15;
        cpa16(sb + (uint32_t)(row * PITCH + c * 16), g_qh + (qbase + row) * KD + c * 8);
    }
}
__device__ __forceinline__ void copy_neg_tile(uint32_t sb, int tid, int stage, int rowbase) {
    uint32_t base = sb + (uint32_t)(QT_BYTES + NT_BYTES * stage);
    #pragma unroll
    for (int j = 0; j < 4; j++) {
        int idx = j * 256 + tid;
        int row = idx >> 4, c = idx & 15;
        cpa16(base + (uint32_t)(row * PITCH + c * 16),
              g_nh + (rowbase + row) * KD + c * 8);
    }
}

// online LSE over one 32x32 warp tile (fp32 MUFU ex2)
__device__ __forceinline__ void epilogue(const float C[2][4][4], float* mrun, float* srun) {
    #pragma unroll
    for (int j = 0; j < 4; j++) {
        const int mi = j >> 1, hi = (j & 1) * 2;
        float x0 = C[mi][0][hi],     x1 = C[mi][0][hi + 1];
        float x2 = C[mi][1][hi],     x3 = C[mi][1][hi + 1];
        float x4 = C[mi][2][hi],     x5 = C[mi][2][hi + 1];
        float x6 = C[mi][3][hi],     x7 = C[mi][3][hi + 1];
        float tmax = fmaxf(fmaxf(fmaxf(x0, x1), fmaxf(x2, x3)),
                           fmaxf(fmaxf(x4, x5), fmaxf(x6, x7)));
        if (tmax > mrun[j]) {
            srun[j] *= ex2f(mrun[j] - tmax);
            mrun[j] = tmax;
        }
        const float mn = mrun[j];
        srun[j] += ex2f(x0 - mn) + ex2f(x1 - mn) + ex2f(x2 - mn) + ex2f(x3 - mn)
                 + ex2f(x4 - mn) + ex2f(x5 - mn) + ex2f(x6 - mn) + ex2f(x7 - mn);
    }
}

__global__ __launch_bounds__(256, 3) void conloss_main_kernel(float* __restrict__ out) {
    extern __shared__ char smem[];
    uint32_t sb = smem_u32(smem);
    const int tid = threadIdx.x, warp = tid >> 5, lane = tid & 31;
    const int wm = warp & 3;          // 4 warp-rows of 32
    const int wn = warp >> 2;         // 2 warp-cols of 32
    const int rb = blockIdx.x;
    const int qbase = rb * MB;
    const int negbase = blockIdx.y * (NNEG / SPLITS);

    const uint32_t mbFull0  = sb + MBAR_BASE;
    const uint32_t mbFull1  = sb + MBAR_BASE + 8;
    const uint32_t mbEmpty0 = sb + MBAR_BASE + 16;
    const uint32_t mbEmpty1 = sb + MBAR_BASE + 24;

    if (tid == 0) {
        MBARRIER_INIT(mbFull0, 256);
        MBARRIER_INIT(mbFull1, 256);
        MBARRIER_INIT(mbEmpty0, 8);
        MBARRIER_INIT(mbEmpty1, 8);
    }
    __syncthreads();                  // mbarriers visible before any arrive

    // prologue: Q + tile0 -> full0 ; tile1 -> full1
    copy_q_block(sb, tid, qbase);
    copy_neg_tile(sb, tid, 0, negbase);
    cpa_arrive(mbFull0);              // fires when Q + tile0 (this thread) land
    copy_neg_tile(sb, tid, 1, negbase + NT);
    cpa_arrive(mbFull1);              // fires when tile1 (and prior) land

    const uint32_t aBase = sb + (uint32_t)((wm * 32 + (lane & 15)) * PITCH + ((lane >> 4) * 16));
    const uint32_t bOff = (uint32_t)(((wn * 32) + (lane & 7) + ((lane >> 4) << 3)) * PITCH
                                     + (((lane >> 3) & 1) * 16));

    float C[2][4][4];
    float mrun[4], srun[4];
    #pragma unroll
    for (int j = 0; j < 4; j++) { mrun[j] = -1e30f; srun[j] = 0.0f; }

    #pragma unroll 1
    for (int t = 0; t < TILES; t++) {
        const int s = t & 1;
        const int par = (t >> 1) & 1;
        const uint32_t mbFull  = s ? mbFull1 : mbFull0;
        const uint32_t mbEmpty = s ? mbEmpty1 : mbEmpty0;

        MBARRIER_WAIT_PARITY(mbFull, par);     // stage s holds tile t

        #pragma unroll
        for (int mi = 0; mi < 2; mi++)
            #pragma unroll
            for (int ni = 0; ni < 4; ni++)
                #pragma unroll
                for (int r = 0; r < 4; r++) C[mi][ni][r] = 0.0f;

        const uint32_t bBase = sb + (uint32_t)(QT_BYTES + NT_BYTES * s) + bOff;

        #pragma unroll
        for (int ks = 0; ks < 8; ks++) {
            uint32_t A[2][4], B[2][4];
            #pragma unroll
            for (int mi = 0; mi < 2; mi++)
                ldsm4(A[mi][0], A[mi][1], A[mi][2], A[mi][3],
                      aBase + (uint32_t)(mi * 16 * PITCH + ks * 32));
            #pragma unroll
            for (int np = 0; np < 2; np++)
                ldsm4(B[np][0], B[np][1], B[np][2], B[np][3],
                      bBase + (uint32_t)(np * 16 * PITCH + ks * 32));
            #pragma unroll
            for (int mi = 0; mi < 2; mi++)
                #pragma unroll
                for (int ni = 0; ni < 4; ni++)
                    mma16816(C[mi][ni], A[mi],
                             B[ni >> 1][(ni & 1) * 2], B[ni >> 1][(ni & 1) * 2 + 1]);
        }
        // all my LDSM smem reads of stage s completed (MMA issue consumed them)
        if (lane == 0) MBARRIER_ARRIVE(mbEmpty);

        epilogue(C, mrun, srun);               // slack while other warps drain

        if (t + 2 < TILES) {
            MBARRIER_WAIT_PARITY(mbEmpty, par);   // all 8 warps done reading s
            copy_neg_tile(sb, tid, s, negbase + (t + 2) * NT);
            cpa_arrive(mbFull);                   // re-arms full[s], flips parity
        }
    }

    // combine the 4 lanes sharing each row
    #pragma unroll
    for (int j = 0; j < 4; j++) {
        #pragma unroll
        for (int off = 1; off <= 2; off <<= 1) {
            float mo = __shfl_xor_sync(0xffffffffu, mrun[j], off);
            float so = __shfl_xor_sync(0xffffffffu, srun[j], off);
            float M = fmaxf(mrun[j], mo);
            srun[j] = srun[j] * ex2f(mrun[j] - M) + so * ex2f(mo - M);
            mrun[j] = M;
        }
    }

    __syncthreads();   // everyone done with smem tiles (incl. Q region)
    float* smm = reinterpret_cast<float*>(smem);          // [2][128]
    float* sms = smm + 256;
    if ((lane & 3) == 0) {
        #pragma unroll
        for (int j = 0; j < 4; j++) {
            int row = wm * 32 + (j >> 1) * 16 + (j & 1) * 8 + (lane >> 2);
            smm[wn * 128 + row] = mrun[j];
            sms[wn * 128 + row] = srun[j];
        }
    }
    __syncthreads();
    if (tid < 128) {
        float m0 = smm[tid], m1 = smm[128 + tid];
        float M = fmaxf(m0, m1);
        float S = sms[tid] * ex2f(m0 - M) + sms[128 + tid] * ex2f(m1 - M);
        int grow = qbase + tid;
        g_pm[blockIdx.y * NQ + grow] = M;
        g_ps[blockIdx.y * NQ + grow] = S;
    }

    // ---------------- fused reduction ----------------
    __threadfence();
    __shared__ int lastRb;
    if (tid == 0)
        lastRb = (atomicAdd(&g_rbctr[rb], 1) == SPLITS - 1);
    __syncthreads();
    if (!lastRb) return;

    __threadfence();
    double part = 0.0;
    if (tid < 128) {
        int r = qbase + tid;
        float m[SPLITS], s[SPLITS];
        #pragma unroll
        for (int j = 0; j < SPLITS; j++) {
            m[j] = g_pm[j * NQ + r];
            s[j] = g_ps[j * NQ + r];
        }
        float M = m[0];
        #pragma unroll
        for (int j = 1; j < SPLITS; j++) M = fmaxf(M, m[j]);
        float S = 0.0f;
        #pragma unroll
        for (int j = 0; j < SPLITS; j++) S += s[j] * ex2f(m[j] - M);
        float lse = LN2F * (M + log2f(S));
        part = (double)(lse - g_poslogit[r]);
    }
    double* shd = reinterpret_cast<double*>(smem);
    shd[tid] = part;
    __syncthreads();
    for (int o = 128; o > 0; o >>= 1) {
        if (tid < o) shd[tid] += shd[tid + o];
        __syncthreads();
    }
    if (tid == 0) {
        g_part[rb] = shd[0];
        g_rbctr[rb] = 0;
        __threadfence();
        if (atomicAdd(&g_ctr, 1) == RB - 1) {
            __threadfence();
            double acc = 0.0;
            #pragma unroll
            for (int i = 0; i < RB; i++) acc += g_part[i];
            out[0] = (float)(acc / (double)NQ);
            g_ctr = 0;
        }
    }
}

// ============================================================================
// kernel_launch
// ============================================================================
extern "C" void kernel_launch(void* const* d_in, const int* in_sizes, int n_in,
                              void* d_out, int out_size) {
    (void)n_in; (void)out_size;
    const float* a0 = (const float*)d_in[0];
    const float* a1 = (const float*)d_in[1];
    const float* a2 = (const float*)d_in[2];
    const float *q, *p, *neg;
    if (in_sizes[2] == NNEG * KD)      { q = a0; p = a1; neg = a2; }
    else if (in_sizes[1] == NNEG * KD) { q = a0; p = a2; neg = a1; }
    else                               { q = a1; p = a2; neg = a0; }

    cudaFuncSetAttribute(conloss_main_kernel,
                         cudaFuncAttributeMaxDynamicSharedMemorySize, SMEM_TOTAL);

    prep_kernel<<<NB_NEG + NQ / 8, 256>>>(q, p, neg);
    conloss_main_kernel<<<dim3(RB, SPLITS), 256, SMEM_TOTAL>>>((float*)d_out);
}

// round 11
// speedup vs baseline: 1.1007x; 1.0162x over previous
#include <cuda_runtime.h>
#include <cuda_fp16.h>
#include <cstdint>

// ============================================================================
// IWConLoss on GB300 (sm_103a via compute_103 baseline PTX):
//   scores = Q @ Neg^T / tau ; loss = mean( LSE_row(scores) - (Q.P)/tau )
// R10 = R6 (best, 102.9us) + CTA tile-phase rotation: co-resident CTAs process
// tiles at offsets 4/8 apart so epilogue (MUFU/FMA) bursts of one CTA overlap
// MMA windows of the others instead of phase-locking SMSP-wide.
// ============================================================================

static constexpr int NQ   = 8192;
static constexpr int NNEG = 16384;
static constexpr int KD   = 128;

static constexpr int MB = 128;      // query rows per CTA
static constexpr int NT = 64;       // negatives per tile
static constexpr int SPLITS = 16;   // grid = 64 x 16 = 1024 CTAs
static constexpr int RB = NQ / MB;  // 64 row blocks
static constexpr int TILES = NNEG / SPLITS / NT;   // 16
static constexpr int STAGES = 2;

static constexpr int PITCH = 272;                   // 128 fp16 + 8 pad
static constexpr int QT_BYTES = 128 * PITCH;        // 34816
static constexpr int NT_BYTES = NT * PITCH;         // 17408
static constexpr int SMEM_TOTAL = QT_BYTES + STAGES * NT_BYTES;  // 69632 -> 3 CTAs/SM

static constexpr float INV_TAU = 5.0f;
static constexpr float C_T  = 7.2134752044448170f;  // log2(e)/tau
static constexpr float LN2F = 0.69314718055994531f;

// ---------------- device scratch ----------------
__device__ __align__(16) __half g_qh[NQ * KD];
__device__ __align__(16) __half g_nh[NNEG * KD];
__device__ float g_poslogit[NQ];
__device__ float g_pm[SPLITS * NQ];     // [split][row]
__device__ float g_ps[SPLITS * NQ];
__device__ double g_part[RB];
__device__ int g_rbctr[RB];
__device__ int g_ctr;

// ---------------- helpers ----------------
__device__ __forceinline__ uint32_t smem_u32(const void* p) {
    uint32_t a;
    asm("{ .reg .u64 t; cvta.to.shared.u64 t, %1; cvt.u32.u64 %0, t; }"
        : "=r"(a) : "l"(p));
    return a;
}
__device__ __forceinline__ float ex2f(float x) {
    float r; asm("ex2.approx.ftz.f32 %0, %1;" : "=f"(r) : "f"(x)); return r;
}
__device__ __forceinline__ void cpa16(uint32_t dst, const void* src) {
    asm volatile("cp.async.cg.shared.global [%0], [%1], 16;" :: "r"(dst), "l"(src));
}
#define CP_COMMIT() asm volatile("cp.async.commit_group;" ::: "memory")
#define CP_WAIT(n)  asm volatile("cp.async.wait_group %0;" :: "n"(n) : "memory")

__device__ __forceinline__ void ldsm4(uint32_t& r0, uint32_t& r1, uint32_t& r2,
                                      uint32_t& r3, uint32_t addr) {
    asm volatile("ldmatrix.sync.aligned.m8n8.x4.shared.b16 {%0,%1,%2,%3}, [%4];"
        : "=r"(r0), "=r"(r1), "=r"(r2), "=r"(r3) : "r"(addr));
}
__device__ __forceinline__ void mma16816(float* d, const uint32_t* a,
                                         const uint32_t b0, const uint32_t b1) {
    asm volatile(
        "mma.sync.aligned.m16n8k16.row.col.f32.f16.f16.f32 "
        "{%0,%1,%2,%3}, {%4,%5,%6,%7}, {%8,%9}, {%0,%1,%2,%3};"
        : "+f"(d[0]), "+f"(d[1]), "+f"(d[2]), "+f"(d[3])
        : "r"(a[0]), "r"(a[1]), "r"(a[2]), "r"(a[3]), "r"(b0), "r"(b1));
}

// ============================================================================
// combined prep kernel
// ============================================================================
static constexpr int NB_NEG = (NNEG * KD) / 1024;   // 2048 blocks

__global__ void prep_kernel(const float* __restrict__ q, const float* __restrict__ pos,
                            const float* __restrict__ neg) {
    if (blockIdx.x < NB_NEG) {
        int i = (blockIdx.x * 256 + threadIdx.x) * 4;
        float4 v = *reinterpret_cast<const float4*>(neg + i);
        __half2* o = reinterpret_cast<__half2*>(g_nh + i);
        o[0] = __floats2half2_rn(v.x, v.y);
        o[1] = __floats2half2_rn(v.z, v.w);
    } else {
        int b = blockIdx.x - NB_NEG;
        int w = threadIdx.x >> 5, lane = threadIdx.x & 31;
        int row = b * 8 + w;
        const float4 q4 = *reinterpret_cast<const float4*>(q + row * KD + lane * 4);
        const float4 p4 = *reinterpret_cast<const float4*>(pos + row * KD + lane * 4);
        float d = q4.x * p4.x + q4.y * p4.y + q4.z * p4.z + q4.w * p4.w;
        #pragma unroll
        for (int o = 16; o > 0; o >>= 1) d += __shfl_xor_sync(0xffffffffu, d, o);
        if (lane == 0) g_poslogit[row] = d * INV_TAU;

        __half2* o = reinterpret_cast<__half2*>(g_qh + row * KD + lane * 4);
        o[0] = __floats2half2_rn(q4.x * C_T, q4.y * C_T);
        o[1] = __floats2half2_rn(q4.z * C_T, q4.w * C_T);
    }
}

// ============================================================================
// main fused kernel
// ============================================================================
__device__ __forceinline__ void copy_q_block(uint32_t sb, int tid, int qbase) {
    #pragma unroll
    for (int j = 0; j < 8; j++) {
        int idx = j * 256 + tid;
        int row = idx >> 4, c = idx & 15;
        cpa16(sb + (uint32_t)(row * PITCH + c * 16), g_qh + (qbase + row) * KD + c * 8);
    }
}
__device__ __forceinline__ void copy_neg_tile(uint32_t sb, int tid, int stage, int rowbase) {
    uint32_t base = sb + (uint32_t)(QT_BYTES + NT_BYTES * stage);
    #pragma unroll
    for (int j = 0; j < 4; j++) {
        int idx = j * 256 + tid;
        int row = idx >> 4, c = idx & 15;
        cpa16(base + (uint32_t)(row * PITCH + c * 16),
              g_nh + (rowbase + row) * KD + c * 8);
    }
}

// online LSE over one 32x32 warp tile (fp32 MUFU ex2)
__device__ __forceinline__ void epilogue(const float C[2][4][4], float* mrun, float* srun) {
    #pragma unroll
    for (int j = 0; j < 4; j++) {
        const int mi = j >> 1, hi = (j & 1) * 2;
        float x0 = C[mi][0][hi],     x1 = C[mi][0][hi + 1];
        float x2 = C[mi][1][hi],     x3 = C[mi][1][hi + 1];
        float x4 = C[mi][2][hi],     x5 = C[mi][2][hi + 1];
        float x6 = C[mi][3][hi],     x7 = C[mi][3][hi + 1];
        float tmax = fmaxf(fmaxf(fmaxf(x0, x1), fmaxf(x2, x3)),
                           fmaxf(fmaxf(x4, x5), fmaxf(x6, x7)));
        if (tmax > mrun[j]) {
            srun[j] *= ex2f(mrun[j] - tmax);
            mrun[j] = tmax;
        }
        const float mn = mrun[j];
        srun[j] += ex2f(x0 - mn) + ex2f(x1 - mn) + ex2f(x2 - mn) + ex2f(x3 - mn)
                 + ex2f(x4 - mn) + ex2f(x5 - mn) + ex2f(x6 - mn) + ex2f(x7 - mn);
    }
}

__global__ __launch_bounds__(256, 3) void conloss_main_kernel(float* __restrict__ out) {
    extern __shared__ char smem[];
    uint32_t sb = smem_u32(smem);
    const int tid = threadIdx.x, warp = tid >> 5, lane = tid & 31;
    const int wm = warp & 3;          // 4 warp-rows of 32
    const int wn = warp >> 2;         // 2 warp-cols of 32
    const bool epiFirst = (warp < 4);
    const int rb = blockIdx.x;
    const int qbase = rb * MB;
    const int negbase = blockIdx.y * (NNEG / SPLITS);
    // Tile-phase rotation: co-resident CTAs (bids ~148 apart -> x ~20 apart)
    // get phases 4 and 8 tiles apart, de-phasing their epilogue bursts.
    const int phase = blockIdx.x & (TILES - 1);

    copy_q_block(sb, tid, qbase);
    copy_neg_tile(sb, tid, 0, negbase + phase * NT);
    CP_COMMIT();
    copy_neg_tile(sb, tid, 1, negbase + ((phase + 1) & (TILES - 1)) * NT);
    CP_COMMIT();

    const uint32_t aBase = sb + (uint32_t)((wm * 32 + (lane & 15)) * PITCH + ((lane >> 4) * 16));
    const uint32_t bOff = (uint32_t)(((wn * 32) + (lane & 7) + ((lane >> 4) << 3)) * PITCH
                                     + (((lane >> 3) & 1) * 16));

    float C[2][4][4];
    float mrun[4], srun[4];
    #pragma unroll
    for (int j = 0; j < 4; j++) { mrun[j] = -1e30f; srun[j] = 0.0f; }

    for (int t = 0; t < TILES; t++) {
        CP_WAIT(STAGES - 1);
        __syncthreads();

        if (epiFirst && t > 0) epilogue(C, mrun, srun);

        #pragma unroll
        for (int mi = 0; mi < 2; mi++)
            #pragma unroll
            for (int ni = 0; ni < 4; ni++)
                #pragma unroll
                for (int r = 0; r < 4; r++) C[mi][ni][r] = 0.0f;

        const uint32_t bBase = sb + (uint32_t)(QT_BYTES + NT_BYTES * (t & 1)) + bOff;

        #pragma unroll
        for (int ks = 0; ks < 8; ks++) {
            uint32_t A[2][4], B[2][4];
            #pragma unroll
            for (int mi = 0; mi < 2; mi++)
                ldsm4(A[mi][0], A[mi][1], A[mi][2], A[mi][3],
                      aBase + (uint32_t)(mi * 16 * PITCH + ks * 32));
            #pragma unroll
            for (int np = 0; np < 2; np++)
                ldsm4(B[np][0], B[np][1], B[np][2], B[np][3],
                      bBase + (uint32_t)(np * 16 * PITCH + ks * 32));
            #pragma unroll
            for (int mi = 0; mi < 2; mi++)
                #pragma unroll
                for (int ni = 0; ni < 4; ni++)
                    mma16816(C[mi][ni], A[mi],
                             B[ni >> 1][(ni & 1) * 2], B[ni >> 1][(ni & 1) * 2 + 1]);
        }
        __syncthreads();

        if (t + STAGES < TILES)
            copy_neg_tile(sb, tid, t & 1,
                          negbase + ((t + STAGES + phase) & (TILES - 1)) * NT);
        CP_COMMIT();

        if (!epiFirst) epilogue(C, mrun, srun);
    }
    if (epiFirst) epilogue(C, mrun, srun);

    // combine the 4 lanes sharing each row
    #pragma unroll
    for (int j = 0; j < 4; j++) {
        #pragma unroll
        for (int off = 1; off <= 2; off <<= 1) {
            float mo = __shfl_xor_sync(0xffffffffu, mrun[j], off);
            float so = __shfl_xor_sync(0xffffffffu, srun[j], off);
            float M = fmaxf(mrun[j], mo);
            srun[j] = srun[j] * ex2f(mrun[j] - M) + so * ex2f(mo - M);
            mrun[j] = M;
        }
    }

    __syncthreads();
    float* smm = reinterpret_cast<float*>(smem);          // [2][128]
    float* sms = smm + 256;
    if ((lane & 3) == 0) {
        #pragma unroll
        for (int j = 0; j < 4; j++) {
            int row = wm * 32 + (j >> 1) * 16 + (j & 1) * 8 + (lane >> 2);
            smm[wn * 128 + row] = mrun[j];
            sms[wn * 128 + row] = srun[j];
        }
    }
    __syncthreads();
    if (tid < 128) {
        float m0 = smm[tid], m1 = smm[128 + tid];
        float M = fmaxf(m0, m1);
        float S = sms[tid] * ex2f(m0 - M) + sms[128 + tid] * ex2f(m1 - M);
        int grow = qbase + tid;
        g_pm[blockIdx.y * NQ + grow] = M;
        g_ps[blockIdx.y * NQ + grow] = S;
    }

    // ---------------- fused reduction ----------------
    __threadfence();
    __shared__ int lastRb;
    if (tid == 0)
        lastRb = (atomicAdd(&g_rbctr[rb], 1) == SPLITS - 1);
    __syncthreads();
    if (!lastRb) return;

    __threadfence();
    double part = 0.0;
    if (tid < 128) {
        int r = qbase + tid;
        float m[SPLITS], s[SPLITS];
        #pragma unroll
        for (int j = 0; j < SPLITS; j++) {
            m[j] = g_pm[j * NQ + r];
            s[j] = g_ps[j * NQ + r];
        }
        float M = m[0];
        #pragma unroll
        for (int j = 1; j < SPLITS; j++) M = fmaxf(M, m[j]);
        float S = 0.0f;
        #pragma unroll
        for (int j = 0; j < SPLITS; j++) S += s[j] * ex2f(m[j] - M);
        float lse = LN2F * (M + log2f(S));
        part = (double)(lse - g_poslogit[r]);
    }
    double* shd = reinterpret_cast<double*>(smem);
    shd[tid] = part;
    __syncthreads();
    for (int o = 128; o > 0; o >>= 1) {
        if (tid < o) shd[tid] += shd[tid + o];
        __syncthreads();
    }
    if (tid == 0) {
        g_part[rb] = shd[0];
        g_rbctr[rb] = 0;
        __threadfence();
        if (atomicAdd(&g_ctr, 1) == RB - 1) {
            __threadfence();
            double acc = 0.0;
            #pragma unroll
            for (int i = 0; i < RB; i++) acc += g_part[i];
            out[0] = (float)(acc / (double)NQ);
            g_ctr = 0;
        }
    }
}

// ============================================================================
// kernel_launch
// ============================================================================
extern "C" void kernel_launch(void* const* d_in, const int* in_sizes, int n_in,
                              void* d_out, int out_size) {
    (void)n_in; (void)out_size;
    const float* a0 = (const float*)d_in[0];
    const float* a1 = (const float*)d_in[1];
    const float* a2 = (const float*)d_in[2];
    const float *q, *p, *neg;
    if (in_sizes[2] == NNEG * KD)      { q = a0; p = a1; neg = a2; }
    else if (in_sizes[1] == NNEG * KD) { q = a0; p = a2; neg = a1; }
    else                               { q = a1; p = a2; neg = a0; }

    cudaFuncSetAttribute(conloss_main_kernel,
                         cudaFuncAttributeMaxDynamicSharedMemorySize, SMEM_TOTAL);

    prep_kernel<<<NB_NEG + NQ / 8, 256>>>(q, p, neg);
    conloss_main_kernel<<<dim3(RB, SPLITS), 256, SMEM_TOTAL>>>((float*)d_out);
}